// round 9
// baseline (speedup 1.0000x reference)
#include <cuda_runtime.h>
#include <math.h>

#define BB 8
#define NN 4096
#define DD 1024
#define HH 1792

#define GRID 592          // 148 SMs x 4 CTAs (forced by launch_bounds(256,4))
#define TPB 256
#define BPB 74            // blocks per batch (592 / 8) in phases A and D
#define NCHU 224          // h-chunks in phase B
#define HPERU 8           // 224 * 8 = 1792
#define CGRP 8            // partials per phase-C block

// Scratch (allocation-free contract): __device__ globals.
__device__ float g_xbar[BB * DD];          // mean_n x  (atomic-accumulated)
__device__ float g_upart[NCHU][BB * DD];   // partial Wq^T @ kbar
__device__ float g_u[BB * DD];             // reduced u (atomic-accumulated)
__device__ float g_c[BB];                  // bq . kbar (atomic-accumulated)
__device__ unsigned g_bar;                 // grid barrier counter

// ---------------------------------------------------------------------------
// K0: reset accumulators + barrier counter (runs before k_main each replay).
__global__ void k_zero() {
    int i = blockIdx.x * blockDim.x + threadIdx.x;
    if (i < BB * DD) { g_xbar[i] = 0.f; g_u[i] = 0.f; }
    if (i < BB) g_c[i] = 0.f;
    if (i == 0) g_bar = 0u;
}

// ---------------------------------------------------------------------------
// Software grid barrier. Safe: all GRID blocks co-resident
// (256 thr x 4 CTAs/SM x 148 SMs = 592; regs 64*1024 = full RF, smem 17KB).
__device__ __forceinline__ void gridbar(unsigned target) {
    __syncthreads();
    if (threadIdx.x == 0) {
        __threadfence();
        atomicAdd(&g_bar, 1u);
        unsigned v;
        do {
            asm volatile("ld.volatile.global.u32 %0, [%1];"
                         : "=r"(v) : "l"(&g_bar));
            if (v < target) __nanosleep(64);
        } while (v < target);
        __threadfence();
    }
    __syncthreads();
}

// ---------------------------------------------------------------------------
__global__ void __launch_bounds__(TPB, 4)
k_main(const float* __restrict__ x,  const float* __restrict__ Wq,
       const float* __restrict__ bq, const float* __restrict__ Wk,
       const float* __restrict__ bk, float* __restrict__ out) {
    const int t = threadIdx.x;
    const int blk = blockIdx.x;
    const int warp = t >> 5, lane = t & 31;
    __shared__ float  s_kb[HPERU][BB];
    __shared__ float4 s_u[DD / 4];            // u[b] staged for phase D

    // ===== Phase A: xbar[b,d] = (1/N) sum_n x[b,n,d] ======================
    {
        const int b = blk / BPB;               // 0..7
        const int c = blk % BPB;
        const int n0 = (c * NN) / BPB;
        const int n1 = ((c + 1) * NN) / BPB;
        const float4* xp = (const float4*)(x + (size_t)b * NN * DD);

        float4 acc = make_float4(0.f, 0.f, 0.f, 0.f);
        int n = n0;
        for (; n + 8 <= n1; n += 8) {
            float4 v[8];
            #pragma unroll
            for (int j = 0; j < 8; j++)
                v[j] = xp[(size_t)(n + j) * (DD / 4) + t];
            #pragma unroll
            for (int j = 0; j < 8; j++) {
                acc.x += v[j].x; acc.y += v[j].y;
                acc.z += v[j].z; acc.w += v[j].w;
            }
        }
        for (; n < n1; n++) {
            float4 v = xp[(size_t)n * (DD / 4) + t];
            acc.x += v.x; acc.y += v.y; acc.z += v.z; acc.w += v.w;
        }
        const float invN = 1.0f / (float)NN;
        float* dst = g_xbar + b * DD + t * 4;
        atomicAdd(dst + 0, acc.x * invN);
        atomicAdd(dst + 1, acc.y * invN);
        atomicAdd(dst + 2, acc.z * invN);
        atomicAdd(dst + 3, acc.w * invN);
    }
    gridbar(GRID);

    // ===== Phase B: kbar chunk (smem) + upart, reg-dieted =================
    if (blk < NCHU) {
        const int hbase = blk * HPERU;
        // -- phase 1: warp w computes kbar[b][h=hbase+w]
        {
            const int h = hbase + warp;
            const float4* wk = (const float4*)(Wk + (size_t)h * DD);
            float acc[BB];
            #pragma unroll
            for (int b = 0; b < BB; b++) acc[b] = 0.f;
            #pragma unroll
            for (int i = 0; i < 8; i++) {
                const float4 w4 = wk[i * 32 + lane];
                #pragma unroll
                for (int b = 0; b < BB; b++) {
                    const float4 xv =
                        ((const float4*)(g_xbar + b * DD))[i * 32 + lane];
                    acc[b] += w4.x * xv.x + w4.y * xv.y
                            + w4.z * xv.z + w4.w * xv.w;
                }
            }
            #pragma unroll
            for (int b = 0; b < BB; b++)
                #pragma unroll
                for (int o = 16; o > 0; o >>= 1)
                    acc[b] += __shfl_xor_sync(0xffffffffu, acc[b], o);

            if (lane < BB) {
                const float kb = acc[lane] + bk[h];  // lane b = kbar[b][h]
                s_kb[warp][lane] = kb;
                atomicAdd(&g_c[lane], bq[h] * kb);
            }
        }
        __syncthreads();

        // -- phase 2: two halves of 4 batches (acc = 16 regs); Wq rows
        //    read twice, second sweep L1-hit (32KB working set).
        #pragma unroll
        for (int half = 0; half < 2; half++) {
            float4 acc[4];
            #pragma unroll
            for (int b = 0; b < 4; b++)
                acc[b] = make_float4(0.f, 0.f, 0.f, 0.f);
            #pragma unroll
            for (int hh = 0; hh < HPERU; hh++) {
                const float4 w =
                    ((const float4*)(Wq + (size_t)(hbase + hh) * DD))[t];
                #pragma unroll
                for (int b = 0; b < 4; b++) {
                    const float kb = s_kb[hh][half * 4 + b];
                    acc[b].x = fmaf(w.x, kb, acc[b].x);
                    acc[b].y = fmaf(w.y, kb, acc[b].y);
                    acc[b].z = fmaf(w.z, kb, acc[b].z);
                    acc[b].w = fmaf(w.w, kb, acc[b].w);
                }
            }
            float4* dst = (float4*)(g_upart[blk]);
            #pragma unroll
            for (int b = 0; b < 4; b++)
                dst[(half * 4 + b) * (DD / 4) + t] = acc[b];
        }
    }
    gridbar(2u * GRID);

    // ===== Phase C: u = sum_c upart[c]  (L2-hot) ==========================
    if (blk < NCHU) {                       // 224 blocks: 8 strips x 28 groups
        const int ib = blk & 7;
        const int cbase = (blk >> 3) * CGRP;
        const int f4 = ib * 256 + t;
        float4 s = make_float4(0.f, 0.f, 0.f, 0.f);
        #pragma unroll
        for (int j = 0; j < CGRP; j++) {
            float4 v = ((const float4*)(g_upart[cbase + j]))[f4];
            s.x += v.x; s.y += v.y; s.z += v.z; s.w += v.w;
        }
        float* dst = g_u + f4 * 4;
        atomicAdd(dst + 0, s.x);
        atomicAdd(dst + 1, s.y);
        atomicAdd(dst + 2, s.z);
        atomicAdd(dst + 3, s.w);
    }
    gridbar(3u * GRID);

    // ===== Phase D: scores; u[b] staged in smem, one row per warp/iter ===
    {
        const int b = blk / BPB;               // 0..7
        const int c = blk % BPB;
        const int n0 = (c * NN) / BPB;
        const int n1 = ((c + 1) * NN) / BPB;

        s_u[t] = ((const float4*)(g_u + b * DD))[t];   // 4 KB
        __syncthreads();

        const float scale = rsqrtf((float)HH);
        const float cb = g_c[b];
        const float* xbase = x + (size_t)b * NN * DD;
        float* obase = out + b * NN;

        for (int n = n0 + warp; n < n1; n += 8) {
            const float4* xp = (const float4*)(xbase + (size_t)n * DD);
            float4 v[8];
            #pragma unroll
            for (int i = 0; i < 8; i++) v[i] = xp[i * 32 + lane];
            float acc = 0.f;
            #pragma unroll
            for (int i = 0; i < 8; i++) {
                const float4 uv = s_u[i * 32 + lane];
                acc += v[i].x * uv.x + v[i].y * uv.y
                     + v[i].z * uv.z + v[i].w * uv.w;
            }
            #pragma unroll
            for (int o = 16; o > 0; o >>= 1)
                acc += __shfl_down_sync(0xffffffffu, acc, o);
            if (lane == 0) obase[n] = scale * (acc + cb);
        }
    }
}

// ---------------------------------------------------------------------------
extern "C" void kernel_launch(void* const* d_in, const int* in_sizes, int n_in,
                              void* d_out, int out_size) {
    const float* x  = (const float*)d_in[0];   // [B, N, D] f32
    const float* Wq = (const float*)d_in[1];   // [H, D]    f32
    const float* bq = (const float*)d_in[2];   // [H]       f32
    const float* Wk = (const float*)d_in[3];   // [H, D]    f32
    const float* bk = (const float*)d_in[4];   // [H]       f32
    float* out = (float*)d_out;                // [B, N]    f32

    k_zero<<<(BB * DD + TPB - 1) / TPB, TPB>>>();
    k_main<<<GRID, TPB>>>(x, Wq, bq, Wk, bk, out);
}

// round 10
// speedup vs baseline: 1.0321x; 1.0321x over previous
#include <cuda_runtime.h>
#include <math.h>

#define BB 8
#define NN 4096
#define DD 1024
#define HH 1792

#define GRID 296          // 148 SMs x 2 CTAs (forced by launch_bounds(256,2))
#define TPB 256
#define BPB 37            // blocks per batch (296 / 8) in phases A and D
#define NCHU 224          // h-chunks in phase B
#define HPERU 8           // 224 * 8 = 1792
#define NU 8              // striped u copies (contention: 28 adds/address)

// Scratch (allocation-free contract): __device__ globals, zero at load.
// INVARIANT: all scratch (except g_bar, which is monotonic) is zero on kernel
// entry — the kernel re-zeroes it after the final barrier each run.
__device__ float g_xbar[BB * DD];          // mean_n x  (atomic-accumulated)
__device__ float g_u8[NU][BB * DD];        // striped u accumulators
__device__ float g_c[BB];                  // bq . kbar (atomic-accumulated)
__device__ unsigned g_bar;                 // monotonic grid-barrier counter

// ---------------------------------------------------------------------------
// Software grid barrier (absolute target). Safe: all GRID blocks co-resident.
__device__ __forceinline__ void gridbar(unsigned target) {
    __syncthreads();
    if (threadIdx.x == 0) {
        __threadfence();
        atomicAdd(&g_bar, 1u);
        unsigned v;
        do {
            asm volatile("ld.volatile.global.u32 %0, [%1];"
                         : "=r"(v) : "l"(&g_bar));
            if (v < target) __nanosleep(64);
        } while (v < target);
        __threadfence();
    }
    __syncthreads();
}

// ---------------------------------------------------------------------------
__global__ void __launch_bounds__(TPB, 2)
k_main(const float* __restrict__ x,  const float* __restrict__ Wq,
       const float* __restrict__ bq, const float* __restrict__ Wk,
       const float* __restrict__ bk, float* __restrict__ out) {
    const int t = threadIdx.x;
    const int blk = blockIdx.x;
    const int warp = t >> 5, lane = t & 31;
    __shared__ float    s_kb[HPERU][BB];
    __shared__ float4   s_u[DD / 4];       // u[b] staged for phase D
    __shared__ unsigned s_base;            // barrier epoch base

    // Epoch base: g_bar is a multiple of 3*GRID between runs; during this
    // run's phase A it can only have advanced by < GRID (bar1 can't release
    // until *this* block arrives), so flooring recovers the base exactly.
    if (t == 0) {
        unsigned v;
        asm volatile("ld.volatile.global.u32 %0, [%1];"
                     : "=r"(v) : "l"(&g_bar));
        s_base = v - (v % (3u * GRID));
    }
    __syncthreads();
    const unsigned base = s_base;

    // ===== Phase A: xbar[b,d] = (1/N) sum_n x[b,n,d]  (unroll 8) ==========
    {
        const int b = blk / BPB;               // 0..7
        const int c = blk % BPB;
        const int n0 = (c * NN) / BPB;
        const int n1 = ((c + 1) * NN) / BPB;
        const float4* xp = (const float4*)(x + (size_t)b * NN * DD);

        float4 acc = make_float4(0.f, 0.f, 0.f, 0.f);
        int n = n0;
        for (; n + 8 <= n1; n += 8) {
            float4 v[8];
            #pragma unroll
            for (int j = 0; j < 8; j++)
                v[j] = xp[(size_t)(n + j) * (DD / 4) + t];
            #pragma unroll
            for (int j = 0; j < 8; j++) {
                acc.x += v[j].x; acc.y += v[j].y;
                acc.z += v[j].z; acc.w += v[j].w;
            }
        }
        for (; n < n1; n++) {
            float4 v = xp[(size_t)n * (DD / 4) + t];
            acc.x += v.x; acc.y += v.y; acc.z += v.z; acc.w += v.w;
        }
        const float invN = 1.0f / (float)NN;
        float* dst = g_xbar + b * DD + t * 4;
        atomicAdd(dst + 0, acc.x * invN);
        atomicAdd(dst + 1, acc.y * invN);
        atomicAdd(dst + 2, acc.z * invN);
        atomicAdd(dst + 3, acc.w * invN);
    }
    gridbar(base + GRID);

    // ===== Phase B: kbar chunk (smem) -> direct striped-u atomics =========
    if (blk < NCHU) {
        const int hbase = blk * HPERU;
        {
            const int h = hbase + warp;
            const float4* wk = (const float4*)(Wk + (size_t)h * DD);
            float4 wreg[8];
            #pragma unroll
            for (int i = 0; i < 8; i++) wreg[i] = wk[i * 32 + lane];

            float acc[BB];
            #pragma unroll
            for (int b = 0; b < BB; b++) {
                const float4* xb = (const float4*)(g_xbar + b * DD);
                float s = 0.f;
                #pragma unroll
                for (int i = 0; i < 8; i++) {
                    float4 xv = xb[i * 32 + lane];
                    s += wreg[i].x * xv.x + wreg[i].y * xv.y
                       + wreg[i].z * xv.z + wreg[i].w * xv.w;
                }
                acc[b] = s;
            }
            #pragma unroll
            for (int b = 0; b < BB; b++)
                #pragma unroll
                for (int o = 16; o > 0; o >>= 1)
                    acc[b] += __shfl_xor_sync(0xffffffffu, acc[b], o);

            if (lane < BB) {
                const float kb = acc[lane] + bk[h];  // lane b = kbar[b][h]
                s_kb[warp][lane] = kb;
                atomicAdd(&g_c[lane], bq[h] * kb);
            }
        }
        __syncthreads();

        float4 acc[BB];
        #pragma unroll
        for (int b = 0; b < BB; b++) acc[b] = make_float4(0.f, 0.f, 0.f, 0.f);
        #pragma unroll
        for (int hh = 0; hh < HPERU; hh++) {
            const float4 w = ((const float4*)(Wq + (size_t)(hbase + hh) * DD))[t];
            #pragma unroll
            for (int b = 0; b < BB; b++) {
                const float kb = s_kb[hh][b];
                acc[b].x = fmaf(w.x, kb, acc[b].x);
                acc[b].y = fmaf(w.y, kb, acc[b].y);
                acc[b].z = fmaf(w.z, kb, acc[b].z);
                acc[b].w = fmaf(w.w, kb, acc[b].w);
            }
        }
        float* ug = g_u8[blk & (NU - 1)];      // stripe: 28 blocks per copy
        #pragma unroll
        for (int b = 0; b < BB; b++) {
            float* dst = ug + b * DD + t * 4;
            atomicAdd(dst + 0, acc[b].x);
            atomicAdd(dst + 1, acc[b].y);
            atomicAdd(dst + 2, acc[b].z);
            atomicAdd(dst + 3, acc[b].w);
        }
    }
    gridbar(base + 2u * GRID);

    // ===== Phase D: stage u[b] (sum of 8 stripes) in smem; score rows =====
    {
        const int b = blk / BPB;               // 0..7
        const int c = blk % BPB;
        const int n0 = (c * NN) / BPB;
        const int n1 = ((c + 1) * NN) / BPB;

        float4 us = make_float4(0.f, 0.f, 0.f, 0.f);
        #pragma unroll
        for (int k = 0; k < NU; k++) {
            float4 v = ((const float4*)(g_u8[k] + b * DD))[t];
            us.x += v.x; us.y += v.y; us.z += v.z; us.w += v.w;
        }
        s_u[t] = us;
        __syncthreads();

        const float scale = rsqrtf((float)HH);
        const float cb = g_c[b];
        const float* xbase = x + (size_t)b * NN * DD;
        float* obase = out + b * NN;

        for (int n = n0 + warp; n < n1; n += 8) {
            const float4* xp = (const float4*)(xbase + (size_t)n * DD);
            float4 v[8];
            #pragma unroll
            for (int i = 0; i < 8; i++) v[i] = xp[i * 32 + lane];
            float acc = 0.f;
            #pragma unroll
            for (int i = 0; i < 8; i++) {
                const float4 uv = s_u[i * 32 + lane];
                acc += v[i].x * uv.x + v[i].y * uv.y
                     + v[i].z * uv.z + v[i].w * uv.w;
            }
            #pragma unroll
            for (int o = 16; o > 0; o >>= 1)
                acc += __shfl_down_sync(0xffffffffu, acc, o);
            if (lane == 0) obase[n] = scale * (acc + cb);
        }
    }
    gridbar(base + 3u * GRID);

    // ===== Cleanup: restore zero-scratch invariant for the next replay ====
    // (all reads of g_xbar/g_u8/g_c complete before bar3; plain stores here
    //  are made visible by kernel completion)
    {
        const int gid = blk * TPB + t;                 // 0 .. 75775
        const int total = BB * DD + NU * BB * DD;      // 73728 floats
        if (gid < BB * DD) g_xbar[gid] = 0.f;
        int i = gid + BB * DD;
        if (i < total) ((float*)g_u8)[gid] = 0.f;      // covers all of g_u8
        if (gid < NU * BB * DD - (total - BB * DD)) {} // (g_u8 fully covered above? no)
        // g_u8 has 65536 floats; threads 0..65535 clear them:
        if (gid < NU * BB * DD) ((float*)g_u8)[gid] = 0.f;
        if (gid < BB) g_c[gid] = 0.f;
    }
}

// ---------------------------------------------------------------------------
extern "C" void kernel_launch(void* const* d_in, const int* in_sizes, int n_in,
                              void* d_out, int out_size) {
    const float* x  = (const float*)d_in[0];   // [B, N, D] f32
    const float* Wq = (const float*)d_in[1];   // [H, D]    f32
    const float* bq = (const float*)d_in[2];   // [H]       f32
    const float* Wk = (const float*)d_in[3];   // [H, D]    f32
    const float* bk = (const float*)d_in[4];   // [H]       f32
    float* out = (float*)d_out;                // [B, N]    f32

    k_main<<<GRID, TPB>>>(x, Wq, bq, Wk, bk, out);
}

// round 11
// speedup vs baseline: 1.1715x; 1.1351x over previous
#include <cuda_runtime.h>
#include <math.h>

#define BB 8
#define NN 4096
#define DD 1024
#define HH 1792

#define GRID 296          // 148 SMs x 2 CTAs (forced by launch_bounds)
#define TPB 256
#define NCHU 256          // h-chunks in phase B
#define HPERU 7           // 256 * 7 = 1792
#define CGRP 8            // partials per phase-C block
#define BLKS_PER_B 37     // 296 / 8 blocks per batch in phase A
#define SMEM_DYN (2 * HPERU * DD * 4)   // s_wk + s_wq = 57344 B

// Scratch (allocation-free contract): __device__ globals.
__device__ float g_xbar[BB * DD];          // mean_n x  (atomic-accumulated)
__device__ float g_upart[NCHU][BB * DD];   // partial Wq^T @ kbar
__device__ float g_u[BB * DD];             // reduced u (atomic-accumulated)
__device__ float g_c[BB];                  // bq . kbar (atomic-accumulated)
__device__ unsigned g_bar;                 // grid barrier counter

// ---------------------------------------------------------------------------
// K0: reset accumulators + barrier counter (runs before k_main each replay).
__global__ void k_zero() {
    int i = blockIdx.x * blockDim.x + threadIdx.x;
    if (i < BB * DD) { g_xbar[i] = 0.f; g_u[i] = 0.f; }
    if (i < BB) g_c[i] = 0.f;
    if (i == 0) g_bar = 0u;
}

// ---------------------------------------------------------------------------
// Software grid barrier. Safe: all GRID blocks co-resident
// (launch_bounds(256,2) on 148 SMs; smem 57KB -> 228/57 = 4 fit).
__device__ __forceinline__ void gridbar(unsigned target) {
    __syncthreads();
    if (threadIdx.x == 0) {
        __threadfence();
        atomicAdd(&g_bar, 1u);
        unsigned v;
        do {
            asm volatile("ld.volatile.global.u32 %0, [%1];"
                         : "=r"(v) : "l"(&g_bar));
            if (v < target) __nanosleep(64);
        } while (v < target);
        __threadfence();
    }
    __syncthreads();
}

// 16-byte async copy global -> shared (bypasses L1, lands in smem).
__device__ __forceinline__ void cp16(void* s, const void* g) {
    unsigned sa = (unsigned)__cvta_generic_to_shared(s);
    asm volatile("cp.async.cg.shared.global [%0], [%1], 16;\n"
                 :: "r"(sa), "l"(g));
}

// ---------------------------------------------------------------------------
__global__ void __launch_bounds__(TPB, 2)
k_main(const float* __restrict__ x,  const float* __restrict__ Wq,
       const float* __restrict__ bq, const float* __restrict__ Wk,
       const float* __restrict__ bk, float* __restrict__ out) {
    const int t = threadIdx.x;
    const int blk = blockIdx.x;
    const int warp = t >> 5, lane = t & 31;
    __shared__ float s_kb[HPERU][BB];

    extern __shared__ float smem[];
    float* s_wk = smem;                   // [HPERU * DD]
    float* s_wq = smem + HPERU * DD;      // [HPERU * DD]

    // ===== Prefetch: phase-B weight chunks -> smem (async, rides under A) =
    if (blk < NCHU) {
        const int hbase = blk * HPERU;
        const float4* wk4 = (const float4*)(Wk + (size_t)hbase * DD);
        const float4* wq4 = (const float4*)(Wq + (size_t)hbase * DD);
        float4* swk4 = (float4*)s_wk;
        float4* swq4 = (float4*)s_wq;
        #pragma unroll
        for (int i = t; i < HPERU * (DD / 4); i += TPB) {
            cp16(&swk4[i], &wk4[i]);
            cp16(&swq4[i], &wq4[i]);
        }
        asm volatile("cp.async.commit_group;\n" ::: "memory");
    }

    // ===== Phase A: xbar[b,d] = (1/N) sum_n x[b,n,d] =====================
    {
        const int b = blk / BLKS_PER_B;            // 0..7
        const int c = blk % BLKS_PER_B;
        const int n0 = (c * NN) / BLKS_PER_B;
        const int n1 = ((c + 1) * NN) / BLKS_PER_B;
        const float4* xp = (const float4*)(x + (size_t)b * NN * DD);

        float4 acc = make_float4(0.f, 0.f, 0.f, 0.f);
        int n = n0;
        for (; n + 8 <= n1; n += 8) {
            #pragma unroll
            for (int j = 0; j < 8; j++) {
                float4 v = xp[(size_t)(n + j) * (DD / 4) + t];
                acc.x += v.x; acc.y += v.y; acc.z += v.z; acc.w += v.w;
            }
        }
        for (; n < n1; n++) {
            float4 v = xp[(size_t)n * (DD / 4) + t];
            acc.x += v.x; acc.y += v.y; acc.z += v.z; acc.w += v.w;
        }
        const float invN = 1.0f / (float)NN;
        float* dst = g_xbar + b * DD + t * 4;
        atomicAdd(dst + 0, acc.x * invN);
        atomicAdd(dst + 1, acc.y * invN);
        atomicAdd(dst + 2, acc.z * invN);
        atomicAdd(dst + 3, acc.w * invN);
    }
    gridbar(GRID);

    // ===== Phase B: kbar chunk (smem weights) + upart ====================
    if (blk < NCHU) {
        asm volatile("cp.async.wait_group 0;\n" ::: "memory");
        __syncthreads();                    // uniform per-block: blk uniform

        if (warp < HPERU) {
            const float4* wk = (const float4*)(s_wk + warp * DD);
            float4 wreg[8];
            #pragma unroll
            for (int i = 0; i < 8; i++) wreg[i] = wk[i * 32 + lane];

            float acc[BB];
            #pragma unroll
            for (int b = 0; b < BB; b++) {
                const float4* xb = (const float4*)(g_xbar + b * DD);
                float s = 0.f;
                #pragma unroll
                for (int i = 0; i < 8; i++) {
                    float4 xv = xb[i * 32 + lane];
                    s += wreg[i].x * xv.x + wreg[i].y * xv.y
                       + wreg[i].z * xv.z + wreg[i].w * xv.w;
                }
                acc[b] = s;
            }
            #pragma unroll
            for (int b = 0; b < BB; b++)
                #pragma unroll
                for (int o = 16; o > 0; o >>= 1)
                    acc[b] += __shfl_xor_sync(0xffffffffu, acc[b], o);

            const int h = blk * HPERU + warp;
            if (lane < BB) {
                const float kb = acc[lane] + bk[h];  // lane b = kbar[b][h]
                s_kb[warp][lane] = kb;
                atomicAdd(&g_c[lane], bq[h] * kb);
            }
        }
        __syncthreads();

        float4 acc[BB];
        #pragma unroll
        for (int b = 0; b < BB; b++) acc[b] = make_float4(0.f, 0.f, 0.f, 0.f);
        #pragma unroll
        for (int hh = 0; hh < HPERU; hh++) {
            const float4 w = ((const float4*)(s_wq + hh * DD))[t];
            #pragma unroll
            for (int b = 0; b < BB; b++) {
                const float kb = s_kb[hh][b];
                acc[b].x = fmaf(w.x, kb, acc[b].x);
                acc[b].y = fmaf(w.y, kb, acc[b].y);
                acc[b].z = fmaf(w.z, kb, acc[b].z);
                acc[b].w = fmaf(w.w, kb, acc[b].w);
            }
        }
        float4* dst = (float4*)(g_upart[blk]);
        #pragma unroll
        for (int b = 0; b < BB; b++) dst[b * (DD / 4) + t] = acc[b];
    }
    gridbar(2u * GRID);

    // ===== Phase C: u = sum_c upart[c]  (L2-hot, same kernel) ============
    if (blk < NCHU) {                       // 256 blocks: 8 strips x 32 groups
        const int ib = blk & 7;
        const int cbase = (blk >> 3) * CGRP;
        const int f4 = ib * 256 + t;
        float4 s = make_float4(0.f, 0.f, 0.f, 0.f);
        #pragma unroll
        for (int j = 0; j < CGRP; j++) {
            float4 v = ((const float4*)(g_upart[cbase + j]))[f4];
            s.x += v.x; s.y += v.y; s.z += v.z; s.w += v.w;
        }
        float* dst = g_u + f4 * 4;
        atomicAdd(dst + 0, s.x);
        atomicAdd(dst + 1, s.y);
        atomicAdd(dst + 2, s.z);
        atomicAdd(dst + 3, s.w);
    }
    gridbar(3u * GRID);

    // ===== Phase D: scores[r] = scale * (x[r].u[b] + c[b]) ===============
    {
        const float scale = rsqrtf((float)HH);
        const int wglobal = blk * 8 + warp;          // 0..2367
        for (int r = wglobal; r < BB * NN; r += GRID * 8) {
            const int b = r >> 12;                   // N = 4096
            const float4* xp = (const float4*)(x + (size_t)r * DD);
            const float4* up = (const float4*)(g_u + b * DD);
            float acc = 0.f;
            #pragma unroll
            for (int i = 0; i < 8; i++) {
                float4 xv = xp[i * 32 + lane];
                float4 uv = up[i * 32 + lane];
                acc += xv.x * uv.x + xv.y * uv.y + xv.z * uv.z + xv.w * uv.w;
            }
            #pragma unroll
            for (int o = 16; o > 0; o >>= 1)
                acc += __shfl_down_sync(0xffffffffu, acc, o);
            if (lane == 0) out[r] = scale * (acc + g_c[b]);
        }
    }
}

// ---------------------------------------------------------------------------
extern "C" void kernel_launch(void* const* d_in, const int* in_sizes, int n_in,
                              void* d_out, int out_size) {
    const float* x  = (const float*)d_in[0];   // [B, N, D] f32
    const float* Wq = (const float*)d_in[1];   // [H, D]    f32
    const float* bq = (const float*)d_in[2];   // [H]       f32
    const float* Wk = (const float*)d_in[3];   // [H, D]    f32
    const float* bk = (const float*)d_in[4];   // [H]       f32
    float* out = (float*)d_out;                // [B, N]    f32

    cudaFuncSetAttribute(k_main, cudaFuncAttributeMaxDynamicSharedMemorySize,
                         SMEM_DYN);
    k_zero<<<(BB * DD + TPB - 1) / TPB, TPB>>>();
    k_main<<<GRID, TPB, SMEM_DYN>>>(x, Wq, bq, Wk, bk, out);
}